// round 13
// baseline (speedup 1.0000x reference)
#include <cuda_runtime.h>

// Problem constants
#define N 256
#define H 1024
#define M 256
#define ZLEN (M + N)   // 512
#define NT 512         // threads per block
#define NW (NT / 32)   // 16 warps

__device__ __forceinline__ float warp_reduce(float v) {
    #pragma unroll
    for (int o = 16; o > 0; o >>= 1)
        v += __shfl_xor_sync(0xffffffffu, v, o);
    return v;
}

__device__ __forceinline__ float dot4(float4 a, float4 b) {
    return a.x * b.x + a.y * b.y + a.z * b.z + a.w * b.w;
}

// One block per node n. Whole pipeline in one kernel; intermediates in smem.
//   phase1: r1[h] = relu(W1[n,h,:] . xmask)            (H outputs)
//   phase2: r2[m] = relu(W2[n,m,:] . r1)               (M outputs)
//   phase3: h[hh] = relu(W3[n,hh,0:M].r2 + W3[n,hh,M+n]*x[n] + b3[n,hh])
//           acc  += W4[n,hh] * h[hh]                   (folded, no h buffer)
//   out[n] = relu(acc + b4[n])
// Converged tuning: unrolls p1=16, p2=2, p3=8 (champion config, 115.2us).
__global__ __launch_bounds__(NT, 2) void fused_all(
    const float* __restrict__ x,
    const float* __restrict__ W1, const float* __restrict__ W2,
    const float* __restrict__ W3, const float* __restrict__ b3,
    const float* __restrict__ W4, const float* __restrict__ b4,
    float* __restrict__ out)
{
    const int n    = blockIdx.x;
    const int tid  = threadIdx.x;
    const int wid  = tid >> 5;
    const int lane = tid & 31;

    __shared__ float4 xs4[N / 4];   // masked x   (1 KB)
    __shared__ float4 r1s[H / 4];   // r1         (4 KB)
    __shared__ float4 r2s[M / 4];   // r2         (1 KB)
    __shared__ float  wsum[NW];

    // Load masked x: element n zeroed
    if (tid < N / 4) {
        float4 v = reinterpret_cast<const float4*>(x)[tid];
        const int base = tid * 4;
        if (n == base + 0) v.x = 0.f;
        if (n == base + 1) v.y = 0.f;
        if (n == base + 2) v.z = 0.f;
        if (n == base + 3) v.w = 0.f;
        xs4[tid] = v;
    }
    __syncthreads();

    // ---- Phase 1: r1 = relu(W1[n] @ xmask), warp-per-row, strided rows ----
    {
        const float4* W1b = reinterpret_cast<const float4*>(
            W1 + (size_t)n * H * N);
        float* r1f = reinterpret_cast<float*>(r1s);
        #pragma unroll 16
        for (int i = 0; i < H / NW; i++) {      // 64 rows per warp
            const int h = wid + i * NW;
            const float4* row = W1b + (size_t)h * (N / 4);
            float acc = dot4(__ldcs(row + lane),      xs4[lane])
                      + dot4(__ldcs(row + lane + 32), xs4[lane + 32]);
            acc = warp_reduce(acc);
            if (lane == 0) r1f[h] = fmaxf(acc, 0.f);
        }
    }
    __syncthreads();

    // ---- Phase 2: r2 = relu(W2[n] @ r1) ----
    {
        const float4* W2b = reinterpret_cast<const float4*>(
            W2 + (size_t)n * M * H);
        float* r2f = reinterpret_cast<float*>(r2s);
        #pragma unroll 2
        for (int i = 0; i < M / NW; i++) {      // 16 rows per warp
            const int m = wid + i * NW;
            const float4* row = W2b + (size_t)m * (H / 4);
            float acc = 0.f;
            #pragma unroll
            for (int k = 0; k < H / 4 / 32; k++)    // 8 float4 per lane
                acc += dot4(__ldcs(row + lane + k * 32), r1s[lane + k * 32]);
            acc = warp_reduce(acc);
            if (lane == 0) r2f[m] = fmaxf(acc, 0.f);
        }
    }
    __syncthreads();

    // ---- Phase 3: h = relu(W3[:,0:M].r2 + onehot + b3); fold W4 ----
    {
        const float* W3b = W3 + (size_t)n * H * ZLEN;
        const float* b3b = b3 + (size_t)n * H;
        const float* W4b = W4 + (size_t)n * H;
        const float  xn  = x[n];

        float wacc = 0.f;   // meaningful on lane 0 only
        #pragma unroll 8
        for (int i = 0; i < H / NW; i++) {      // 64 rows per warp
            const int hh = wid + i * NW;
            const float* rowf = W3b + (size_t)hh * ZLEN;
            const float4* row = reinterpret_cast<const float4*>(rowf);
            float acc = dot4(__ldcs(row + lane),      r2s[lane])
                      + dot4(__ldcs(row + lane + 32), r2s[lane + 32]);
            acc = warp_reduce(acc);
            if (lane == 0) {
                float hv = fmaxf(acc + rowf[M + n] * xn + b3b[hh], 0.f);
                wacc += hv * W4b[hh];
            }
        }
        if (lane == 0) wsum[wid] = wacc;
    }
    __syncthreads();

    if (tid == 0) {
        float s = 0.f;
        #pragma unroll
        for (int i = 0; i < NW; i++) s += wsum[i];
        out[n] = fmaxf(s + b4[n], 0.f);
    }
}

extern "C" void kernel_launch(void* const* d_in, const int* in_sizes, int n_in,
                              void* d_out, int out_size)
{
    // Input order (metadata): x, W1, W2, W3, b3, W4, b4, t
    const float* x  = (const float*)d_in[0];
    const float* W1 = (const float*)d_in[1];
    const float* W2 = (const float*)d_in[2];
    const float* W3 = (const float*)d_in[3];
    const float* b3 = (const float*)d_in[4];
    const float* W4 = (const float*)d_in[5];
    const float* b4 = (const float*)d_in[6];
    float* out = (float*)d_out;

    fused_all<<<N, NT>>>(x, W1, W2, W3, b3, W4, b4, out);
}

// round 14
// speedup vs baseline: 1.0162x; 1.0162x over previous
#include <cuda_runtime.h>

// Problem constants
#define N 256
#define H 1024
#define M 256
#define ZLEN (M + N)   // 512
#define NT 512         // threads per block
#define NW (NT / 32)   // 16 warps

__device__ __forceinline__ float warp_reduce(float v) {
    #pragma unroll
    for (int o = 16; o > 0; o >>= 1)
        v += __shfl_xor_sync(0xffffffffu, v, o);
    return v;
}

__device__ __forceinline__ float dot4(float4 a, float4 b) {
    return a.x * b.x + a.y * b.y + a.z * b.z + a.w * b.w;
}

// One block per node n. Whole pipeline in one kernel; intermediates in smem.
//   phase1: r1[h] = relu(W1[n,h,:] . xmask)   — xmask held in registers
//   phase2: r2[m] = relu(W2[n,m,:] . r1)
//   phase3: h[hh] = relu(W3[n,hh,0:M].r2 + W3[n,hh,M+n]*x[n] + b3[n,hh])
//           acc  += W4[n,hh] * h[hh]          (folded, no h buffer)
//   out[n] = relu(acc + b4[n])
// Tuned unrolls: p1=16, p2=2, p3=8 (champion); phase-1 x in regs (no LDS,
// no prologue barrier).
__global__ __launch_bounds__(NT, 2) void fused_all(
    const float* __restrict__ x,
    const float* __restrict__ W1, const float* __restrict__ W2,
    const float* __restrict__ W3, const float* __restrict__ b3,
    const float* __restrict__ W4, const float* __restrict__ b4,
    float* __restrict__ out)
{
    const int n    = blockIdx.x;
    const int tid  = threadIdx.x;
    const int wid  = tid >> 5;
    const int lane = tid & 31;

    __shared__ float4 r1s[H / 4];   // r1         (4 KB)
    __shared__ float4 r2s[M / 4];   // r2         (1 KB)
    __shared__ float  wsum[NW];

    // Masked x in registers (x is 1 KB; L1-resident after first access).
    // xv0 = x[4*lane .. +3], xv1 = x[128 + 4*lane .. +3]; element n zeroed.
    float4 xv0 = __ldg(reinterpret_cast<const float4*>(x) + lane);
    float4 xv1 = __ldg(reinterpret_cast<const float4*>(x) + lane + 32);
    {
        const int b0 = 4 * lane;
        if (n == b0 + 0) xv0.x = 0.f;
        if (n == b0 + 1) xv0.y = 0.f;
        if (n == b0 + 2) xv0.z = 0.f;
        if (n == b0 + 3) xv0.w = 0.f;
        const int b1 = 128 + 4 * lane;
        if (n == b1 + 0) xv1.x = 0.f;
        if (n == b1 + 1) xv1.y = 0.f;
        if (n == b1 + 2) xv1.z = 0.f;
        if (n == b1 + 3) xv1.w = 0.f;
    }

    // ---- Phase 1: r1 = relu(W1[n] @ xmask), warp-per-row, strided rows ----
    {
        const float4* W1b = reinterpret_cast<const float4*>(
            W1 + (size_t)n * H * N);
        float* r1f = reinterpret_cast<float*>(r1s);
        #pragma unroll 16
        for (int i = 0; i < H / NW; i++) {      // 64 rows per warp
            const int h = wid + i * NW;
            const float4* row = W1b + (size_t)h * (N / 4);
            float acc = dot4(__ldcs(row + lane),      xv0)
                      + dot4(__ldcs(row + lane + 32), xv1);
            acc = warp_reduce(acc);
            if (lane == 0) r1f[h] = fmaxf(acc, 0.f);
        }
    }
    __syncthreads();

    // ---- Phase 2: r2 = relu(W2[n] @ r1) ----
    {
        const float4* W2b = reinterpret_cast<const float4*>(
            W2 + (size_t)n * M * H);
        float* r2f = reinterpret_cast<float*>(r2s);
        #pragma unroll 2
        for (int i = 0; i < M / NW; i++) {      // 16 rows per warp
            const int m = wid + i * NW;
            const float4* row = W2b + (size_t)m * (H / 4);
            float acc = 0.f;
            #pragma unroll
            for (int k = 0; k < H / 4 / 32; k++)    // 8 float4 per lane
                acc += dot4(__ldcs(row + lane + k * 32), r1s[lane + k * 32]);
            acc = warp_reduce(acc);
            if (lane == 0) r2f[m] = fmaxf(acc, 0.f);
        }
    }
    __syncthreads();

    // ---- Phase 3: h = relu(W3[:,0:M].r2 + onehot + b3); fold W4 ----
    {
        const float* W3b = W3 + (size_t)n * H * ZLEN;
        const float* b3b = b3 + (size_t)n * H;
        const float* W4b = W4 + (size_t)n * H;
        const float  xn  = __ldg(x + n);

        float wacc = 0.f;   // meaningful on lane 0 only
        #pragma unroll 8
        for (int i = 0; i < H / NW; i++) {      // 64 rows per warp
            const int hh = wid + i * NW;
            const float* rowf = W3b + (size_t)hh * ZLEN;
            const float4* row = reinterpret_cast<const float4*>(rowf);
            float acc = dot4(__ldcs(row + lane),      r2s[lane])
                      + dot4(__ldcs(row + lane + 32), r2s[lane + 32]);
            acc = warp_reduce(acc);
            if (lane == 0) {
                float hv = fmaxf(acc + rowf[M + n] * xn + b3b[hh], 0.f);
                wacc += hv * W4b[hh];
            }
        }
        if (lane == 0) wsum[wid] = wacc;
    }
    __syncthreads();

    if (tid == 0) {
        float s = 0.f;
        #pragma unroll
        for (int i = 0; i < NW; i++) s += wsum[i];
        out[n] = fmaxf(s + b4[n], 0.f);
    }
}

extern "C" void kernel_launch(void* const* d_in, const int* in_sizes, int n_in,
                              void* d_out, int out_size)
{
    // Input order (metadata): x, W1, W2, W3, b3, W4, b4, t
    const float* x  = (const float*)d_in[0];
    const float* W1 = (const float*)d_in[1];
    const float* W2 = (const float*)d_in[2];
    const float* W3 = (const float*)d_in[3];
    const float* b3 = (const float*)d_in[4];
    const float* W4 = (const float*)d_in[5];
    const float* b4 = (const float*)d_in[6];
    float* out = (float*)d_out;

    fused_all<<<N, NT>>>(x, W1, W2, W3, b3, W4, b4, out);
}